// round 2
// baseline (speedup 1.0000x reference)
#include <cuda_runtime.h>
#include <math.h>

// Problem constants (from reference: B=2, S=2048, D=1024, H=16, Dk=64)
#define BB 2
#define SS 2048
#define DD 1024
#define HH 16
#define DK 64
#define BH (BB*HH)

// log2(e)/8 folded into Q projection so softmax uses exp2 (single MUFU.EX2)
#define QSCALE (0.125f * 1.44269504088896340736f)

// ---- static device scratch (no allocation allowed) ----
__device__ float g_Qh[BH*SS*DK];     // 16 MB, head-major, pre-scaled by QSCALE
__device__ float g_Kh[BH*SS*DK];     // 16 MB, head-major
__device__ float g_lb[BH*SS];        // log2 of softmax denominator, compact-q index
__device__ float g_w [BH*SS];        // column sums of softmax matrix (per key)
__device__ float g_ypart[16*BB*HH*DD];
__device__ float g_y [BB*HH*DD];     // y[b,h,j] = sum_k w[b,h,k]*v[b,k,j]
__device__ float g_cs[BB*DD];        // concat_sum
__device__ int   g_qidx[BB*SS];      // compacted valid query indices
__device__ int   g_cnt [BB];
__device__ float g_cntf[BB];

// ---------------------------------------------------------------------------
// Kernel 0: deterministic mask compaction (one block per batch)
// ---------------------------------------------------------------------------
__global__ void k_compact(const int* __restrict__ mask) {
    int b = blockIdx.x;
    int tid = threadIdx.x;                 // 256 threads, 8 elems each
    __shared__ int cnts[256];
    __shared__ int offs[256];
    int base = tid * 8;
    int loc[8];
    int c = 0;
#pragma unroll
    for (int i = 0; i < 8; i++) { loc[i] = mask[b*SS + base + i]; c += (loc[i] != 0); }
    cnts[tid] = c;
    __syncthreads();
    if (tid == 0) {
        int run = 0;
        for (int i = 0; i < 256; i++) { offs[i] = run; run += cnts[i]; }
        g_cnt[b] = run;
        g_cntf[b] = (float)run;
    }
    __syncthreads();
    int o = offs[tid];
#pragma unroll
    for (int i = 0; i < 8; i++) {
        if (loc[i] != 0) { g_qidx[b*SS + o] = base + i; o++; }
    }
}

// ---------------------------------------------------------------------------
// Kernel 1: projection GEMM  Out = (X[4096,1024] @ W[1024,1024] + bias)*scale
// scattered into head-major layout [b,h,s,dk]. Block tile 128x64, thread 8x4.
// which==0 -> g_Qh, which==1 -> g_Kh
// ---------------------------------------------------------------------------
__global__ __launch_bounds__(256) void k_proj(
    const float* __restrict__ X, const float* __restrict__ W,
    const float* __restrict__ bias, float scale, int which)
{
    __shared__ float As[16][128];   // [k][m]
    __shared__ float Bs[16][64];    // [k][n]
    float* Out = which ? g_Kh : g_Qh;

    int tid = threadIdx.x;
    int tx = tid & 15, ty = tid >> 4;
    int m0 = blockIdx.x * 128;
    int n0 = blockIdx.y * 64;

    float acc[8][4];
#pragma unroll
    for (int i = 0; i < 8; i++)
#pragma unroll
        for (int j = 0; j < 4; j++) acc[i][j] = 0.f;

    for (int k0 = 0; k0 < 1024; k0 += 16) {
        // load A tile (128 rows x 16 k) transposed into As[k][m]
#pragma unroll
        for (int i = 0; i < 2; i++) {
            int idx = tid * 2 + i;           // 0..511 float4s
            int r   = idx >> 2;              // row within tile
            int kq  = idx & 3;               // which float4 of the 16 k's
            float4 va = *(const float4*)(X + (size_t)(m0 + r) * 1024 + k0 + kq * 4);
            As[kq*4+0][r] = va.x; As[kq*4+1][r] = va.y;
            As[kq*4+2][r] = va.z; As[kq*4+3][r] = va.w;
        }
        {
            int kr = tid >> 4;               // 0..15
            int c4 = tid & 15;
            *(float4*)(&Bs[kr][c4*4]) =
                *(const float4*)(W + (size_t)(k0 + kr) * 1024 + n0 + c4 * 4);
        }
        __syncthreads();
#pragma unroll
        for (int kk = 0; kk < 16; kk++) {
            float a[8], bb[4];
#pragma unroll
            for (int i = 0; i < 8; i++) a[i] = As[kk][ty*8 + i];
#pragma unroll
            for (int j = 0; j < 4; j++) bb[j] = Bs[kk][tx*4 + j];
#pragma unroll
            for (int i = 0; i < 8; i++)
#pragma unroll
                for (int j = 0; j < 4; j++) acc[i][j] += a[i] * bb[j];
        }
        __syncthreads();
    }
    // epilogue: scatter to head-major [((b*H+h)*S + s)*64 + dd]
#pragma unroll
    for (int i = 0; i < 8; i++) {
        int row = m0 + ty*8 + i;
        int b = row >> 11, s = row & 2047;
#pragma unroll
        for (int j = 0; j < 4; j++) {
            int col = n0 + tx*4 + j;
            int h = col >> 6, dd = col & 63;
            Out[(((size_t)(b*HH + h) * SS + s) << 6) + dd] =
                (acc[i][j] + bias[col]) * scale;
        }
    }
}

// ---------------------------------------------------------------------------
// Kernel 2 (pass A): per (b,h, compact-q tile of 64), compute
//   lb[q] = log2( sum_k 2^(Qs.Ks) )  over all 2048 keys.
// 64x64 score tile per key iteration, 4x4 per thread.
// ---------------------------------------------------------------------------
__global__ __launch_bounds__(256) void k_lsum() {
    int qt = blockIdx.x;          // 0..31
    int bh = blockIdx.y;          // 0..31
    int b  = bh >> 4;
    int cnt = g_cnt[b];
    if (qt * 64 >= cnt) return;

    __shared__ float Qs[64][64];  // [d][q]
    __shared__ float Ks[64][64];  // [d][k]
    __shared__ float red[64][16];

    int tid = threadIdx.x;
    int tx = tid & 15, ty = tid >> 4;
    const float* Qbase = g_Qh + (size_t)bh * SS * 64;
    const float* Kbase = g_Kh + (size_t)bh * SS * 64;

    // gather 64 compacted Q rows, transposed into Qs[d][q]
#pragma unroll
    for (int i = 0; i < 4; i++) {
        int idx = tid + 256 * i;      // 0..1023 float4s
        int q = idx >> 4, d4 = idx & 15;
        int ci = qt * 64 + q;
        float4 vq = make_float4(0.f, 0.f, 0.f, 0.f);
        if (ci < cnt) {
            int s = g_qidx[b*SS + ci];
            vq = *(const float4*)(Qbase + ((size_t)s << 6) + d4 * 4);
        }
        Qs[d4*4+0][q] = vq.x; Qs[d4*4+1][q] = vq.y;
        Qs[d4*4+2][q] = vq.z; Qs[d4*4+3][q] = vq.w;
    }

    float rsum[4] = {0.f, 0.f, 0.f, 0.f};
    for (int kt = 0; kt < 32; kt++) {
#pragma unroll
        for (int i = 0; i < 4; i++) {
            int idx = tid + 256 * i;
            int r = idx >> 4, d4 = idx & 15;
            float4 vk = *(const float4*)(Kbase + ((size_t)(kt*64 + r) << 6) + d4 * 4);
            Ks[d4*4+0][r] = vk.x; Ks[d4*4+1][r] = vk.y;
            Ks[d4*4+2][r] = vk.z; Ks[d4*4+3][r] = vk.w;
        }
        __syncthreads();
        float sc[4][4];
#pragma unroll
        for (int i = 0; i < 4; i++)
#pragma unroll
            for (int j = 0; j < 4; j++) sc[i][j] = 0.f;
#pragma unroll 16
        for (int d = 0; d < 64; d++) {
            float a[4], bb[4];
#pragma unroll
            for (int i = 0; i < 4; i++) a[i]  = Qs[d][ty*4 + i];
#pragma unroll
            for (int j = 0; j < 4; j++) bb[j] = Ks[d][tx*4 + j];
#pragma unroll
            for (int i = 0; i < 4; i++)
#pragma unroll
                for (int j = 0; j < 4; j++) sc[i][j] += a[i] * bb[j];
        }
#pragma unroll
        for (int i = 0; i < 4; i++)
#pragma unroll
            for (int j = 0; j < 4; j++) rsum[i] += exp2f(sc[i][j]);
        __syncthreads();
    }
    // reduce per-q partial sums across the 16 tx threads
#pragma unroll
    for (int i = 0; i < 4; i++) red[ty*4 + i][tx] = rsum[i];
    __syncthreads();
    if (tid < 64) {
        float l = 0.f;
#pragma unroll
        for (int t = 0; t < 16; t++) l += red[tid][t];
        int ci = qt * 64 + tid;
        if (ci < cnt) g_lb[bh*SS + ci] = log2f(l);
    }
}

// ---------------------------------------------------------------------------
// Kernel 3 (pass B): per (b,h, key tile of 64), accumulate column sums
//   w[k] = sum_{valid q} 2^( Qs.Ks - lb[q] )
// Always writes w (zeros if cnt==0) for graph-replay determinism.
// ---------------------------------------------------------------------------
__global__ __launch_bounds__(256) void k_wsum() {
    int kt = blockIdx.x;          // 0..31
    int bh = blockIdx.y;
    int b  = bh >> 4;
    int cnt = g_cnt[b];

    __shared__ float Ks[64][64];
    __shared__ float Qs[64][64];
    __shared__ float lbs[64];
    __shared__ float red[64][16];

    int tid = threadIdx.x;
    int tx = tid & 15, ty = tid >> 4;
    const float* Qbase = g_Qh + (size_t)bh * SS * 64;
    const float* Kbase = g_Kh + (size_t)bh * SS * 64;

#pragma unroll
    for (int i = 0; i < 4; i++) {
        int idx = tid + 256 * i;
        int r = idx >> 4, d4 = idx & 15;
        float4 vk = *(const float4*)(Kbase + ((size_t)(kt*64 + r) << 6) + d4 * 4);
        Ks[d4*4+0][r] = vk.x; Ks[d4*4+1][r] = vk.y;
        Ks[d4*4+2][r] = vk.z; Ks[d4*4+3][r] = vk.w;
    }

    float wacc[4] = {0.f, 0.f, 0.f, 0.f};
    int nqt = (cnt + 63) >> 6;
    for (int qt = 0; qt < nqt; qt++) {
        __syncthreads();   // protect Qs/lbs from previous iteration's readers
#pragma unroll
        for (int i = 0; i < 4; i++) {
            int idx = tid + 256 * i;
            int q = idx >> 4, d4 = idx & 15;
            int ci = qt * 64 + q;
            float4 vq = make_float4(0.f, 0.f, 0.f, 0.f);
            if (ci < cnt) {
                int s = g_qidx[b*SS + ci];
                vq = *(const float4*)(Qbase + ((size_t)s << 6) + d4 * 4);
            }
            Qs[d4*4+0][q] = vq.x; Qs[d4*4+1][q] = vq.y;
            Qs[d4*4+2][q] = vq.z; Qs[d4*4+3][q] = vq.w;
        }
        if (tid < 64) {
            int ci = qt * 64 + tid;
            lbs[tid] = (ci < cnt) ? g_lb[bh*SS + ci] : 1e9f;
        }
        __syncthreads();
        float sc[4][4];
#pragma unroll
        for (int i = 0; i < 4; i++)
#pragma unroll
            for (int j = 0; j < 4; j++) sc[i][j] = 0.f;
#pragma unroll 16
        for (int d = 0; d < 64; d++) {
            float a[4], bb[4];
#pragma unroll
            for (int i = 0; i < 4; i++) a[i]  = Qs[d][ty*4 + i];
#pragma unroll
            for (int j = 0; j < 4; j++) bb[j] = Ks[d][tx*4 + j];
#pragma unroll
            for (int i = 0; i < 4; i++)
#pragma unroll
                for (int j = 0; j < 4; j++) sc[i][j] += a[i] * bb[j];
        }
#pragma unroll
        for (int i = 0; i < 4; i++) {
            float lb = lbs[ty*4 + i];
#pragma unroll
            for (int j = 0; j < 4; j++) wacc[j] += exp2f(sc[i][j] - lb);
        }
    }
    __syncthreads();
    // reduce per-key partials across the 16 ty threads
#pragma unroll
    for (int j = 0; j < 4; j++) red[tx*4 + j][ty] = wacc[j];
    __syncthreads();
    if (tid < 64) {
        float w = 0.f;
#pragma unroll
        for (int t = 0; t < 16; t++) w += red[tid][t];
        g_w[bh*SS + kt*64 + tid] = w;
    }
}

// ---------------------------------------------------------------------------
// Kernel 4: y[b,h,j] = sum_k w[b,h,k] * v[b,k,j]   (split-k partials, then reduce)
// grid.x encodes (b, jtile(4 of 256), ktile(16 of 128))
// ---------------------------------------------------------------------------
__global__ __launch_bounds__(256) void k_ypart(const float* __restrict__ v) {
    int id = blockIdx.x;
    int kt = id & 15;
    int jt = (id >> 4) & 3;
    int b  = id >> 6;
    __shared__ float wsh[16][128];
    int tid = threadIdx.x;
#pragma unroll
    for (int i = 0; i < 8; i++) {
        int idx = tid + 256 * i;       // 0..2047
        int h = idx >> 7, kk = idx & 127;
        wsh[h][kk] = g_w[(b*HH + h) * SS + kt*128 + kk];
    }
    __syncthreads();
    int j = jt * 256 + tid;
    float acc[16];
#pragma unroll
    for (int h = 0; h < 16; h++) acc[h] = 0.f;
    const float* vb = v + ((size_t)b * SS + kt*128) * 1024 + j;
    for (int kk = 0; kk < 128; kk++) {
        float vv = vb[(size_t)kk * 1024];
#pragma unroll
        for (int h = 0; h < 16; h++) acc[h] += wsh[h][kk] * vv;
    }
#pragma unroll
    for (int h = 0; h < 16; h++)
        g_ypart[((size_t)(kt*BB + b) * HH + h) * DD + j] = acc[h];
}

__global__ void k_yred() {
    int i = blockIdx.x * 256 + threadIdx.x;      // 0..32767
    float s = 0.f;
#pragma unroll
    for (int kt = 0; kt < 16; kt++) s += g_ypart[(size_t)kt * (BB*HH*DD) + i];
    g_y[i] = s;
}

// ---------------------------------------------------------------------------
// Kernel 5: cs[b,c] = sum_j y[b,h(c),j]*Wv[j,c] + cnt_b*bv[c]
// ---------------------------------------------------------------------------
__global__ void k_cs(const float* __restrict__ Wv, const float* __restrict__ bv) {
    int idx = blockIdx.x * 256 + threadIdx.x;   // 0..2047
    int b = idx >> 10, c = idx & 1023;
    int h = c >> 6;
    const float* yrow = g_y + (size_t)(b*HH + h) * DD;
    float s = 0.f;
#pragma unroll 8
    for (int j = 0; j < 1024; j++) s += yrow[j] * Wv[(size_t)j * 1024 + c];
    g_cs[idx] = s + g_cntf[b] * bv[c];
}

// ---------------------------------------------------------------------------
// Kernel 6: out[b,d] = sum_c cs[b,c]*Wo[c,d] + cnt_b*bo[d]
// ---------------------------------------------------------------------------
__global__ void k_out(const float* __restrict__ Wo, const float* __restrict__ bo,
                      float* __restrict__ out) {
    int idx = blockIdx.x * 256 + threadIdx.x;   // 0..2047
    int b = idx >> 10, d = idx & 1023;
    const float* cs = g_cs + (size_t)b * 1024;
    float s = 0.f;
#pragma unroll 8
    for (int c = 0; c < 1024; c++) s += cs[c] * Wo[(size_t)c * 1024 + d];
    out[idx] = s + g_cntf[b] * bo[d];
}

// ---------------------------------------------------------------------------
// launch — inputs per metadata order:
// 0:q 1:k 2:v 3:mask 4:Wq 5:bq 6:Wk 7:bk 8:Wv 9:bv 10:Wo 11:bo
// ---------------------------------------------------------------------------
extern "C" void kernel_launch(void* const* d_in, const int* in_sizes, int n_in,
                              void* d_out, int out_size) {
    const float* q    = (const float*)d_in[0];
    const float* k    = (const float*)d_in[1];
    const float* v    = (const float*)d_in[2];
    const int*   mask = (const int*)  d_in[3];
    const float* Wq   = (const float*)d_in[4];
    const float* bq   = (const float*)d_in[5];
    const float* Wk   = (const float*)d_in[6];
    const float* bk   = (const float*)d_in[7];
    const float* Wv   = (const float*)d_in[8];
    const float* bv   = (const float*)d_in[9];
    const float* Wo   = (const float*)d_in[10];
    const float* bo   = (const float*)d_in[11];
    float* out = (float*)d_out;

    k_compact<<<BB, 256>>>(mask);
    k_proj<<<dim3(32, 16), 256>>>(q, Wq, bq, QSCALE, 0);
    k_proj<<<dim3(32, 16), 256>>>(k, Wk, bk, 1.0f, 1);
    k_lsum<<<dim3(32, 32), 256>>>();
    k_wsum<<<dim3(32, 32), 256>>>();
    k_ypart<<<128, 256>>>(v);
    k_yred<<<128, 256>>>();
    k_cs<<<8, 256>>>(Wv, bv);
    k_out<<<8, 256>>>(Wo, bo, out);
}

// round 4
// speedup vs baseline: 1.1626x; 1.1626x over previous
#include <cuda_runtime.h>
#include <math.h>

// Problem constants (B=2, S=2048, D=1024, H=16, Dk=64)
#define BB 2
#define SS 2048
#define DD 1024
#define HH 16
#define DK 64
#define BH (BB*HH)

#define QSCALE (0.125f * 1.44269504088896340736f)

// ---- static device scratch ----
__device__ float g_Qh[BH*SS*DK];
__device__ float g_Kh[BH*SS*DK];
__device__ float g_lb[BH*SS];
__device__ float g_w [BH*SS];
__device__ float g_ypart[16*BB*HH*DD];
__device__ float g_y [BB*HH*DD];
__device__ float g_cs[BB*DD];
__device__ int   g_qidx[BB*SS];
__device__ int   g_cnt [BB];
__device__ float g_cntf[BB];

// ---------------------------------------------------------------------------
// Kernel 0: deterministic mask compaction
// ---------------------------------------------------------------------------
__global__ void k_compact(const int* __restrict__ mask) {
    int b = blockIdx.x;
    int tid = threadIdx.x;
    __shared__ int cnts[256];
    __shared__ int offs[256];
    int base = tid * 8;
    int loc[8];
    int c = 0;
#pragma unroll
    for (int i = 0; i < 8; i++) { loc[i] = mask[b*SS + base + i]; c += (loc[i] != 0); }
    cnts[tid] = c;
    __syncthreads();
    if (tid == 0) {
        int run = 0;
        for (int i = 0; i < 256; i++) { offs[i] = run; run += cnts[i]; }
        g_cnt[b] = run;
        g_cntf[b] = (float)run;
    }
    __syncthreads();
    int o = offs[tid];
#pragma unroll
    for (int i = 0; i < 8; i++) {
        if (loc[i] != 0) { g_qidx[b*SS + o] = base + i; o++; }
    }
}

// ---------------------------------------------------------------------------
// Kernel 1: projection GEMM, 128x128 tile, 8x8 per thread, float4 smem loads
// ---------------------------------------------------------------------------
__global__ __launch_bounds__(256) void k_proj(
    const float* __restrict__ X, const float* __restrict__ W,
    const float* __restrict__ bias, float scale, int which)
{
    __shared__ __align__(16) float As[16][128];   // [k][m]
    __shared__ __align__(16) float Bs[16][128];   // [k][n]
    float* Out = which ? g_Kh : g_Qh;

    int tid = threadIdx.x;
    int tx = tid & 15, ty = tid >> 4;
    int m0 = blockIdx.x * 128;
    int n0 = blockIdx.y * 128;

    float acc[8][8];
#pragma unroll
    for (int i = 0; i < 8; i++)
#pragma unroll
        for (int j = 0; j < 8; j++) acc[i][j] = 0.f;

    for (int k0 = 0; k0 < 1024; k0 += 16) {
#pragma unroll
        for (int i = 0; i < 2; i++) {
            int idx = tid * 2 + i;           // 0..511 float4s
            int r   = idx >> 2;
            int kq  = idx & 3;
            float4 va = *(const float4*)(X + (size_t)(m0 + r) * 1024 + k0 + kq * 4);
            As[kq*4+0][r] = va.x; As[kq*4+1][r] = va.y;
            As[kq*4+2][r] = va.z; As[kq*4+3][r] = va.w;
        }
#pragma unroll
        for (int i = 0; i < 2; i++) {
            int idx = tid * 2 + i;           // 0..511 float4s
            int kr = idx >> 5;               // 0..15
            int c4 = idx & 31;
            *(float4*)(&Bs[kr][c4*4]) =
                *(const float4*)(W + (size_t)(k0 + kr) * 1024 + n0 + c4 * 4);
        }
        __syncthreads();
#pragma unroll
        for (int kk = 0; kk < 16; kk++) {
            float4 a0 = *(const float4*)(&As[kk][ty*8]);
            float4 a1 = *(const float4*)(&As[kk][ty*8+4]);
            float4 b0 = *(const float4*)(&Bs[kk][tx*8]);
            float4 b1 = *(const float4*)(&Bs[kk][tx*8+4]);
            float a[8] = {a0.x,a0.y,a0.z,a0.w,a1.x,a1.y,a1.z,a1.w};
            float bb[8] = {b0.x,b0.y,b0.z,b0.w,b1.x,b1.y,b1.z,b1.w};
#pragma unroll
            for (int i = 0; i < 8; i++)
#pragma unroll
                for (int j = 0; j < 8; j++) acc[i][j] += a[i] * bb[j];
        }
        __syncthreads();
    }
#pragma unroll
    for (int i = 0; i < 8; i++) {
        int row = m0 + ty*8 + i;
        int b = row >> 11, s = row & 2047;
#pragma unroll
        for (int j = 0; j < 8; j++) {
            int col = n0 + tx*8 + j;
            int h = col >> 6, dd = col & 63;
            Out[(((size_t)(b*HH + h) * SS + s) << 6) + dd] =
                (acc[i][j] + bias[col]) * scale;
        }
    }
}

// ---------------------------------------------------------------------------
// Kernel 2 (pass A): 128q x 128k tiles, 8x8 per thread.
// dyn smem: Qs[64*128] | Ks[64*128] | red[128*16]   (73728 B)
// ---------------------------------------------------------------------------
__global__ __launch_bounds__(256) void k_lsum() {
    extern __shared__ __align__(16) float sm[];
    float* Qs  = sm;              // [d][q] 64x128
    float* Ks  = sm + 8192;       // [d][k] 64x128
    float* red = sm + 16384;      // [q][16]

    int qt = blockIdx.x;          // 0..15
    int bh = blockIdx.y;          // 0..31
    int b  = bh >> 4;
    int cnt = g_cnt[b];
    if (qt * 128 >= cnt) return;

    int tid = threadIdx.x;
    int tx = tid & 15, ty = tid >> 4;
    const float* Qbase = g_Qh + (size_t)bh * SS * 64;
    const float* Kbase = g_Kh + (size_t)bh * SS * 64;

    // gather 128 compacted Q rows into Qs[d][q]
#pragma unroll
    for (int i = 0; i < 8; i++) {
        int idx = tid + 256 * i;       // 0..2047 float4s
        int qq = idx >> 4, d4 = idx & 15;
        int ci = qt * 128 + qq;
        float4 vq = make_float4(0.f, 0.f, 0.f, 0.f);
        if (ci < cnt) {
            int s = g_qidx[b*SS + ci];
            vq = *(const float4*)(Qbase + ((size_t)s << 6) + d4 * 4);
        }
        Qs[(d4*4+0)*128 + qq] = vq.x; Qs[(d4*4+1)*128 + qq] = vq.y;
        Qs[(d4*4+2)*128 + qq] = vq.z; Qs[(d4*4+3)*128 + qq] = vq.w;
    }

    float rsum[8];
#pragma unroll
    for (int i = 0; i < 8; i++) rsum[i] = 0.f;

    for (int kt = 0; kt < 16; kt++) {
#pragma unroll
        for (int i = 0; i < 8; i++) {
            int idx = tid + 256 * i;
            int r = idx >> 4, d4 = idx & 15;
            float4 vk = *(const float4*)(Kbase + ((size_t)(kt*128 + r) << 6) + d4 * 4);
            Ks[(d4*4+0)*128 + r] = vk.x; Ks[(d4*4+1)*128 + r] = vk.y;
            Ks[(d4*4+2)*128 + r] = vk.z; Ks[(d4*4+3)*128 + r] = vk.w;
        }
        __syncthreads();
        float sc[8][8];
#pragma unroll
        for (int i = 0; i < 8; i++)
#pragma unroll
            for (int j = 0; j < 8; j++) sc[i][j] = 0.f;
#pragma unroll 4
        for (int d = 0; d < 64; d++) {
            float4 a0 = *(const float4*)(Qs + d*128 + ty*8);
            float4 a1 = *(const float4*)(Qs + d*128 + ty*8 + 4);
            float4 b0 = *(const float4*)(Ks + d*128 + tx*8);
            float4 b1 = *(const float4*)(Ks + d*128 + tx*8 + 4);
            float a[8] = {a0.x,a0.y,a0.z,a0.w,a1.x,a1.y,a1.z,a1.w};
            float bb[8] = {b0.x,b0.y,b0.z,b0.w,b1.x,b1.y,b1.z,b1.w};
#pragma unroll
            for (int i = 0; i < 8; i++)
#pragma unroll
                for (int j = 0; j < 8; j++) sc[i][j] += a[i] * bb[j];
        }
#pragma unroll
        for (int i = 0; i < 8; i++)
#pragma unroll
            for (int j = 0; j < 8; j++) rsum[i] += exp2f(sc[i][j]);
        __syncthreads();
    }
#pragma unroll
    for (int i = 0; i < 8; i++) red[(ty*8 + i)*16 + tx] = rsum[i];
    __syncthreads();
    if (tid < 128) {
        float l = 0.f;
#pragma unroll
        for (int t = 0; t < 16; t++) l += red[tid*16 + t];
        int ci = qt * 128 + tid;
        if (ci < cnt) g_lb[bh*SS + ci] = log2f(l);
    }
}

// ---------------------------------------------------------------------------
// Kernel 3 (pass B): per key tile of 128, column sums of softmax.
// dyn smem: Ks[64*128] | Qs[64*128] | red[128*16] | lbs[128]  (74240 B)
// ---------------------------------------------------------------------------
__global__ __launch_bounds__(256) void k_wsum() {
    extern __shared__ __align__(16) float sm[];
    float* Ks  = sm;
    float* Qs  = sm + 8192;
    float* red = sm + 16384;
    float* lbs = sm + 16384 + 2048;

    int kt = blockIdx.x;          // 0..15
    int bh = blockIdx.y;
    int b  = bh >> 4;
    int cnt = g_cnt[b];

    int tid = threadIdx.x;
    int tx = tid & 15, ty = tid >> 4;
    const float* Qbase = g_Qh + (size_t)bh * SS * 64;
    const float* Kbase = g_Kh + (size_t)bh * SS * 64;

#pragma unroll
    for (int i = 0; i < 8; i++) {
        int idx = tid + 256 * i;
        int r = idx >> 4, d4 = idx & 15;
        float4 vk = *(const float4*)(Kbase + ((size_t)(kt*128 + r) << 6) + d4 * 4);
        Ks[(d4*4+0)*128 + r] = vk.x; Ks[(d4*4+1)*128 + r] = vk.y;
        Ks[(d4*4+2)*128 + r] = vk.z; Ks[(d4*4+3)*128 + r] = vk.w;
    }

    float wacc[8];
#pragma unroll
    for (int j = 0; j < 8; j++) wacc[j] = 0.f;

    int nqt = (cnt + 127) >> 7;
    for (int qt = 0; qt < nqt; qt++) {
        __syncthreads();   // protect Qs/lbs from previous iteration's readers
#pragma unroll
        for (int i = 0; i < 8; i++) {
            int idx = tid + 256 * i;
            int qq = idx >> 4, d4 = idx & 15;
            int ci = qt * 128 + qq;
            float4 vq = make_float4(0.f, 0.f, 0.f, 0.f);
            if (ci < cnt) {
                int s = g_qidx[b*SS + ci];
                vq = *(const float4*)(Qbase + ((size_t)s << 6) + d4 * 4);
            }
            Qs[(d4*4+0)*128 + qq] = vq.x; Qs[(d4*4+1)*128 + qq] = vq.y;
            Qs[(d4*4+2)*128 + qq] = vq.z; Qs[(d4*4+3)*128 + qq] = vq.w;
        }
        if (tid < 128) {
            int ci = qt * 128 + tid;
            lbs[tid] = (ci < cnt) ? g_lb[bh*SS + ci] : 1e9f;
        }
        __syncthreads();
        float sc[8][8];
#pragma unroll
        for (int i = 0; i < 8; i++)
#pragma unroll
            for (int j = 0; j < 8; j++) sc[i][j] = 0.f;
#pragma unroll 4
        for (int d = 0; d < 64; d++) {
            float4 a0 = *(const float4*)(Qs + d*128 + ty*8);
            float4 a1 = *(const float4*)(Qs + d*128 + ty*8 + 4);
            float4 b0 = *(const float4*)(Ks + d*128 + tx*8);
            float4 b1 = *(const float4*)(Ks + d*128 + tx*8 + 4);
            float a[8] = {a0.x,a0.y,a0.z,a0.w,a1.x,a1.y,a1.z,a1.w};
            float bb[8] = {b0.x,b0.y,b0.z,b0.w,b1.x,b1.y,b1.z,b1.w};
#pragma unroll
            for (int i = 0; i < 8; i++)
#pragma unroll
                for (int j = 0; j < 8; j++) sc[i][j] += a[i] * bb[j];
        }
#pragma unroll
        for (int i = 0; i < 8; i++) {
            float lb = lbs[ty*8 + i];
#pragma unroll
            for (int j = 0; j < 8; j++) wacc[j] += exp2f(sc[i][j] - lb);
        }
    }
    __syncthreads();
#pragma unroll
    for (int j = 0; j < 8; j++) red[(tx*8 + j)*16 + ty] = wacc[j];
    __syncthreads();
    if (tid < 128) {
        float w = 0.f;
#pragma unroll
        for (int t = 0; t < 16; t++) w += red[tid*16 + t];
        g_w[bh*SS + kt*128 + tid] = w;
    }
}

// ---------------------------------------------------------------------------
// Kernel 4: y[b,h,j] = sum_k w[b,h,k] * v[b,k,j]
// ---------------------------------------------------------------------------
__global__ __launch_bounds__(256) void k_ypart(const float* __restrict__ v) {
    int id = blockIdx.x;
    int kt = id & 15;
    int jt = (id >> 4) & 3;
    int b  = id >> 6;
    __shared__ float wsh[16][128];
    int tid = threadIdx.x;
#pragma unroll
    for (int i = 0; i < 8; i++) {
        int idx = tid + 256 * i;
        int h = idx >> 7, kk = idx & 127;
        wsh[h][kk] = g_w[(b*HH + h) * SS + kt*128 + kk];
    }
    __syncthreads();
    int j = jt * 256 + tid;
    float acc[16];
#pragma unroll
    for (int h = 0; h < 16; h++) acc[h] = 0.f;
    const float* vb = v + ((size_t)b * SS + kt*128) * 1024 + j;
    for (int kk = 0; kk < 128; kk++) {
        float vv = vb[(size_t)kk * 1024];
#pragma unroll
        for (int h = 0; h < 16; h++) acc[h] += wsh[h][kk] * vv;
    }
#pragma unroll
    for (int h = 0; h < 16; h++)
        g_ypart[((size_t)(kt*BB + b) * HH + h) * DD + j] = acc[h];
}

__global__ void k_yred() {
    int i = blockIdx.x * 256 + threadIdx.x;
    float s = 0.f;
#pragma unroll
    for (int kt = 0; kt < 16; kt++) s += g_ypart[(size_t)kt * (BB*HH*DD) + i];
    g_y[i] = s;
}

// ---------------------------------------------------------------------------
// Kernel 5: cs[b,c] = sum_j y[b,h(c),j]*Wv[j,c] + cnt_b*bv[c]
// ---------------------------------------------------------------------------
__global__ void k_cs(const float* __restrict__ Wv, const float* __restrict__ bv) {
    int idx = blockIdx.x * 256 + threadIdx.x;
    int b = idx >> 10, c = idx & 1023;
    int h = c >> 6;
    const float* yrow = g_y + (size_t)(b*HH + h) * DD;
    float s = 0.f;
#pragma unroll 8
    for (int j = 0; j < 1024; j++) s += yrow[j] * Wv[(size_t)j * 1024 + c];
    g_cs[idx] = s + g_cntf[b] * bv[c];
}

// ---------------------------------------------------------------------------
// Kernel 6: out[b,d] = sum_c cs[b,c]*Wo[c,d] + cnt_b*bo[d]
// ---------------------------------------------------------------------------
__global__ void k_out(const float* __restrict__ Wo, const float* __restrict__ bo,
                      float* __restrict__ out) {
    int idx = blockIdx.x * 256 + threadIdx.x;
    int b = idx >> 10, d = idx & 1023;
    const float* cs = g_cs + (size_t)b * 1024;
    float s = 0.f;
#pragma unroll 8
    for (int c = 0; c < 1024; c++) s += cs[c] * Wo[(size_t)c * 1024 + d];
    out[idx] = s + g_cntf[b] * bo[d];
}

// ---------------------------------------------------------------------------
extern "C" void kernel_launch(void* const* d_in, const int* in_sizes, int n_in,
                              void* d_out, int out_size) {
    const float* q    = (const float*)d_in[0];
    const float* k    = (const float*)d_in[1];
    const float* v    = (const float*)d_in[2];
    const int*   mask = (const int*)  d_in[3];
    const float* Wq   = (const float*)d_in[4];
    const float* bq   = (const float*)d_in[5];
    const float* Wk   = (const float*)d_in[6];
    const float* bk   = (const float*)d_in[7];
    const float* Wv   = (const float*)d_in[8];
    const float* bv   = (const float*)d_in[9];
    const float* Wo   = (const float*)d_in[10];
    const float* bo   = (const float*)d_in[11];
    float* out = (float*)d_out;

    cudaFuncSetAttribute(k_lsum, cudaFuncAttributeMaxDynamicSharedMemorySize, 73728);
    cudaFuncSetAttribute(k_wsum, cudaFuncAttributeMaxDynamicSharedMemorySize, 74240);

    k_compact<<<BB, 256>>>(mask);
    k_proj<<<dim3(32, 8), 256>>>(q, Wq, bq, QSCALE, 0);
    k_proj<<<dim3(32, 8), 256>>>(k, Wk, bk, 1.0f, 1);
    k_lsum<<<dim3(16, 32), 256, 73728>>>();
    k_wsum<<<dim3(16, 32), 256, 74240>>>();
    k_ypart<<<128, 256>>>(v);
    k_yred<<<128, 256>>>();
    k_cs<<<8, 256>>>(Wv, bv);
    k_out<<<8, 256>>>(Wo, bo, out);
}